// round 4
// baseline (speedup 1.0000x reference)
#include <cuda_runtime.h>
#include <math.h>

// Problem constants
#define NN    65536          // nodes
#define EE    1048576        // edges
#define BG    128            // graphs
#define NPG   512            // nodes per graph
#define KSEL  256            // top-k kept
#define NHID  128

// ---------------- device scratch (no allocations allowed) ----------------
__device__ __align__(16) float g_tmp[NN * 128];     // GEMM output per layer
__device__ __align__(16) float g_H[NN * 384];       // concat(h1,h2,h3)
__device__ float g_dis[NN];
__device__ __align__(16) int g_cnt[NN];
__device__ int   g_start[NN];
__device__ int   g_cursor[NN];
__device__ int   g_esrc[EE];
__device__ int   g_bsum[64];
__device__ float g_stmp[NN];
__device__ float g_score[NN];
__device__ __align__(16) float g_read[BG * 768];
__device__ __align__(16) float g_z1[BG * 256];
__device__ __align__(16) float g_z2[BG * 128];

// ---------------- CSR build ----------------
__global__ void k_zero_cnt() {
    int i = blockIdx.x * blockDim.x + threadIdx.x;   // 16384 threads, int4 each
    *reinterpret_cast<int4*>(g_cnt + i * 4) = make_int4(0, 0, 0, 0);
}

__global__ void k_count(const int* __restrict__ dst) {
    int e = blockIdx.x * blockDim.x + threadIdx.x;
    if (e < EE) atomicAdd(&g_cnt[dst[e]], 1);
}

__global__ __launch_bounds__(1024) void k_scan1() {
    __shared__ int s[1024];
    int gi = blockIdx.x * 1024 + threadIdx.x;
    int v = g_cnt[gi];
    s[threadIdx.x] = v;
    __syncthreads();
#pragma unroll
    for (int off = 1; off < 1024; off <<= 1) {
        int t = (threadIdx.x >= off) ? s[threadIdx.x - off] : 0;
        __syncthreads();
        s[threadIdx.x] += t;
        __syncthreads();
    }
    g_start[gi] = s[threadIdx.x] - v;   // local exclusive
    if (threadIdx.x == 1023) g_bsum[blockIdx.x] = s[1023];
}

__global__ void k_scan2() {
    if (threadIdx.x == 0) {
        int acc = 0;
        for (int i = 0; i < 64; i++) { int t = g_bsum[i]; g_bsum[i] = acc; acc += t; }
    }
}

// finalize scan + compute dis = rsqrt(deg+1) in one pass
__global__ void k_scan3() {
    int gi = blockIdx.x * blockDim.x + threadIdx.x;
    if (gi < NN) {
        int s = g_start[gi] + g_bsum[gi >> 10];
        g_start[gi]  = s;
        g_cursor[gi] = s;
        g_dis[gi] = rsqrtf((float)g_cnt[gi] + 1.0f);
    }
}

__global__ void k_scatter(const int* __restrict__ src, const int* __restrict__ dst) {
    int e = blockIdx.x * blockDim.x + threadIdx.x;
    if (e < EE) {
        int d = dst[e];
        int pos = atomicAdd(&g_cursor[d], 1);
        g_esrc[pos] = src[e];
    }
}

// ---------------- GEMM: C[N,128] = A[N,128(stride lda)] @ W[128,128] ----------------
// 128x128 tile per block, 256 threads, 8x8 register microtile, BK=16.
__global__ __launch_bounds__(256) void gemm128(const float* __restrict__ Aext,
                                               int useH, int colOff, int lda,
                                               const float* __restrict__ W) {
    __shared__ float As[16][128];   // [k][row]
    __shared__ float Bs[16][128];   // [k][col]
    const float* A = useH ? (g_H + colOff) : Aext;
    const int tid = threadIdx.x;
    const int row0 = blockIdx.x * 128;
    const int tx = tid & 15, ty = tid >> 4;

    float acc[8][8];
#pragma unroll
    for (int i = 0; i < 8; i++)
#pragma unroll
        for (int j = 0; j < 8; j++) acc[i][j] = 0.f;

    for (int k0 = 0; k0 < 128; k0 += 16) {
#pragma unroll
        for (int l = 0; l < 2; l++) {
            int f = tid * 2 + l;
            int r = f >> 2;
            int kq = (f & 3) * 4;
            float4 v = *reinterpret_cast<const float4*>(A + (size_t)(row0 + r) * lda + k0 + kq);
            As[kq + 0][r] = v.x; As[kq + 1][r] = v.y;
            As[kq + 2][r] = v.z; As[kq + 3][r] = v.w;
        }
#pragma unroll
        for (int l = 0; l < 2; l++) {
            int f = tid * 2 + l;
            int kk = f >> 5;
            int c = (f & 31) * 4;
            *reinterpret_cast<float4*>(&Bs[kk][c]) =
                *reinterpret_cast<const float4*>(W + (size_t)(k0 + kk) * 128 + c);
        }
        __syncthreads();
#pragma unroll
        for (int kk = 0; kk < 16; kk++) {
            float a[8], b[8];
            *(float4*)&a[0] = *(float4*)&As[kk][ty * 8];
            *(float4*)&a[4] = *(float4*)&As[kk][ty * 8 + 4];
            *(float4*)&b[0] = *(float4*)&Bs[kk][tx * 8];
            *(float4*)&b[4] = *(float4*)&Bs[kk][tx * 8 + 4];
#pragma unroll
            for (int i = 0; i < 8; i++)
#pragma unroll
                for (int j = 0; j < 8; j++) acc[i][j] += a[i] * b[j];
        }
        __syncthreads();
    }
#pragma unroll
    for (int i = 0; i < 8; i++) {
        int r = row0 + ty * 8 + i;
        *(float4*)(g_tmp + (size_t)r * 128 + tx * 8) =
            make_float4(acc[i][0], acc[i][1], acc[i][2], acc[i][3]);
        *(float4*)(g_tmp + (size_t)r * 128 + tx * 8 + 4) =
            make_float4(acc[i][4], acc[i][5], acc[i][6], acc[i][7]);
    }
}

// ---------------- GCN aggregation: warp per node, float4 per lane ----------------
// 256 threads = 8 warps = 8 nodes per block; lane covers 4 features.
// Next-iteration index/weight prefetched ahead of current row FMAs to break
// the esrc->dis->row serial chain (MLP 1 -> ~2 on the latency-critical path).
__global__ __launch_bounds__(256) void k_agg(const float* __restrict__ bias, int colOff) {
    int warp = (blockIdx.x * blockDim.x + threadIdx.x) >> 5;
    int lane = threadIdx.x & 31;
    if (warp >= NN) return;
    const int i = warp;
    float di = g_dis[i];
    float4 acc = *reinterpret_cast<const float4*>(g_tmp + (size_t)i * 128 + lane * 4);
    float self = di * di;
    acc.x *= self; acc.y *= self; acc.z *= self; acc.w *= self;
    int s = g_start[i];
    int n = g_cnt[i];
    if (n > 0) {
        int sn = g_esrc[s];
        float w = g_dis[sn] * di;
        for (int p = 1; p < n; p++) {
            int sn_next = g_esrc[s + p];          // prefetch next index
            float w_next = g_dis[sn_next] * di;   // and its weight
            float4 v = *reinterpret_cast<const float4*>(g_tmp + (size_t)sn * 128 + lane * 4);
            acc.x += v.x * w; acc.y += v.y * w;
            acc.z += v.z * w; acc.w += v.w * w;
            sn = sn_next; w = w_next;
        }
        float4 v = *reinterpret_cast<const float4*>(g_tmp + (size_t)sn * 128 + lane * 4);
        acc.x += v.x * w; acc.y += v.y * w;
        acc.z += v.z * w; acc.w += v.w * w;
    }
    float4 bv = *reinterpret_cast<const float4*>(bias + lane * 4);
    acc.x = fmaxf(acc.x + bv.x, 0.f);
    acc.y = fmaxf(acc.y + bv.y, 0.f);
    acc.z = fmaxf(acc.z + bv.z, 0.f);
    acc.w = fmaxf(acc.w + bv.w, 0.f);
    *reinterpret_cast<float4*>(g_H + (size_t)i * 384 + colOff + lane * 4) = acc;
}

// ---------------- score GEMV: warp per node, H[N,384] @ Ws[384] ----------------
__global__ __launch_bounds__(256) void k_sgemv(const float* __restrict__ Ws) {
    int gtid = blockIdx.x * blockDim.x + threadIdx.x;
    int node = gtid >> 5;
    int lane = gtid & 31;
    const float* h = g_H + (size_t)node * 384;
    float p = 0.f;
#pragma unroll
    for (int q = 0; q < 3; q++) {
        float4 hv = *reinterpret_cast<const float4*>(h + q * 128 + lane * 4);
        float4 wv = *reinterpret_cast<const float4*>(Ws + q * 128 + lane * 4);
        p += hv.x * wv.x + hv.y * wv.y + hv.z * wv.z + hv.w * wv.w;
    }
#pragma unroll
    for (int o = 16; o; o >>= 1) p += __shfl_down_sync(0xffffffff, p, o);
    if (lane == 0) g_stmp[node] = p;
}

__global__ void k_sagg(const float* __restrict__ bs) {
    int i = blockIdx.x * blockDim.x + threadIdx.x;
    if (i >= NN) return;
    float di = g_dis[i];
    float acc = g_stmp[i] * di * di;
    int s = g_start[i], n = g_cnt[i];
    if (n > 0) {
        int sn = g_esrc[s];
        for (int p = 1; p < n; p++) {
            int sn_next = g_esrc[s + p];
            acc += g_stmp[sn] * g_dis[sn] * di;
            sn = sn_next;
        }
        acc += g_stmp[sn] * g_dis[sn] * di;
    }
    g_score[i] = acc + bs[0];
}

// ---------------- top-k + gate + max/mean readout: block per graph ----------------
__global__ __launch_bounds__(512) void k_pool() {
    __shared__ float sc[512];
    __shared__ float gate[512];
    __shared__ unsigned char sel[512];
    int g = blockIdx.x, t = threadIdx.x;
    float my = g_score[g * NPG + t];
    sc[t] = my;
    __syncthreads();
    int rank = 0;
#pragma unroll 8
    for (int j = 0; j < NPG; j++) {
        float o = sc[j];
        rank += (o > my) || (o == my && j < t);
    }
    sel[t]  = (rank < KSEL) ? 1 : 0;
    gate[t] = tanhf(my);
    __syncthreads();
    if (t < 384) {
        float mx = -3.4e38f, sm = 0.f;
        const float* base = g_H + (size_t)g * NPG * 384 + t;
        for (int n = 0; n < NPG; n++) {
            if (sel[n]) {
                float v = base[(size_t)n * 384] * gate[n];
                mx = fmaxf(mx, v);
                sm += v;
            }
        }
        g_read[g * 768 + t]       = mx;
        g_read[g * 768 + 384 + t] = sm * (1.0f / KSEL);
    }
}

// ---------------- MLP ----------------
__global__ __launch_bounds__(256) void k_mlp1(const float* __restrict__ W, const float* __restrict__ b) {
    __shared__ float r[768];
    int g = blockIdx.x, t = threadIdx.x;
    for (int k = t; k < 768; k += 256) r[k] = g_read[g * 768 + k];
    __syncthreads();
    float acc = b[t];
#pragma unroll 8
    for (int k = 0; k < 768; k++) acc += r[k] * W[(size_t)k * 256 + t];
    g_z1[g * 256 + t] = fmaxf(acc, 0.f);
}

__global__ __launch_bounds__(128) void k_mlp2(const float* __restrict__ W, const float* __restrict__ b) {
    __shared__ float r[256];
    int g = blockIdx.x, t = threadIdx.x;
    for (int k = t; k < 256; k += 128) r[k] = g_z1[g * 256 + k];
    __syncthreads();
    float acc = b[t];
#pragma unroll 8
    for (int k = 0; k < 256; k++) acc += r[k] * W[(size_t)k * 128 + t];
    g_z2[g * 128 + t] = fmaxf(acc, 0.f);
}

__global__ __launch_bounds__(32) void k_mlp3(const float* __restrict__ W, const float* __restrict__ b,
                                             float* __restrict__ out) {
    int g = blockIdx.x;
    int lane = threadIdx.x;
    __shared__ float logits[10];
    for (int c = 0; c < 10; c++) {
        float p = 0.f;
        for (int k = lane; k < 128; k += 32) p += g_z2[g * 128 + k] * W[k * 10 + c];
#pragma unroll
        for (int o = 16; o; o >>= 1) p += __shfl_down_sync(0xffffffff, p, o);
        if (lane == 0) logits[c] = p + b[c];
    }
    __syncwarp();
    if (lane == 0) {
        float m = logits[0];
        for (int c = 1; c < 10; c++) m = fmaxf(m, logits[c]);
        float s = 0.f;
        for (int c = 0; c < 10; c++) s += expf(logits[c] - m);
        float lse = logf(s);
        for (int c = 0; c < 10; c++) out[g * 10 + c] = logits[c] - m - lse;
    }
}

// ---------------- launch ----------------
extern "C" void kernel_launch(void* const* d_in, const int* in_sizes, int n_in,
                              void* d_out, int out_size) {
    const float* x   = (const float*)d_in[0];
    const int*   ei  = (const int*)  d_in[1];
    const float* W1  = (const float*)d_in[2];
    const float* b1  = (const float*)d_in[3];
    const float* W2  = (const float*)d_in[4];
    const float* b2  = (const float*)d_in[5];
    const float* W3  = (const float*)d_in[6];
    const float* b3  = (const float*)d_in[7];
    const float* Ws  = (const float*)d_in[8];
    const float* bs  = (const float*)d_in[9];
    const float* Wl1 = (const float*)d_in[10];
    const float* bl1 = (const float*)d_in[11];
    const float* Wl2 = (const float*)d_in[12];
    const float* bl2 = (const float*)d_in[13];
    const float* Wl3 = (const float*)d_in[14];
    const float* bl3 = (const float*)d_in[15];
    float* out = (float*)d_out;

    const int* src = ei;
    const int* dst = ei + EE;

    // CSR build + degree norm
    k_zero_cnt<<<64, 256>>>();
    k_count<<<EE / 256, 256>>>(dst);
    k_scan1<<<NN / 1024, 1024>>>();
    k_scan2<<<1, 32>>>();
    k_scan3<<<NN / 256, 256>>>();
    k_scatter<<<EE / 256, 256>>>(src, dst);

    // GCN layer 1: x -> H[:,0:128]
    gemm128<<<NN / 128, 256>>>(x, 0, 0, 128, W1);
    k_agg<<<NN / 8, 256>>>(b1, 0);
    // GCN layer 2: H[:,0:128] -> H[:,128:256]
    gemm128<<<NN / 128, 256>>>(nullptr, 1, 0, 384, W2);
    k_agg<<<NN / 8, 256>>>(b2, 128);
    // GCN layer 3: H[:,128:256] -> H[:,256:384]
    gemm128<<<NN / 128, 256>>>(nullptr, 1, 128, 384, W3);
    k_agg<<<NN / 8, 256>>>(b3, 256);

    // score conv
    k_sgemv<<<(NN * 32) / 256, 256>>>(Ws);
    k_sagg<<<NN / 256, 256>>>(bs);

    // top-k + gated max/mean readout
    k_pool<<<BG, 512>>>();

    // MLP head
    k_mlp1<<<BG, 256>>>(Wl1, bl1);
    k_mlp2<<<BG, 128>>>(Wl2, bl2);
    k_mlp3<<<BG, 32>>>(Wl3, bl3, out);
}